// round 1
// baseline (speedup 1.0000x reference)
#include <cuda_runtime.h>

#define S_LEN  2048
#define BATCH  4
#define EMBED  1024
#define HEADS  16
#define HDIM   64
#define MROWS  (BATCH * S_LEN)   // 8192

// Scratch (allocation-free): Q, K, V, attention output. 4 x 32 MB.
__device__ __align__(16) float g_Q[MROWS * EMBED];
__device__ __align__(16) float g_K[MROWS * EMBED];
__device__ __align__(16) float g_V[MROWS * EMBED];
__device__ __align__(16) float g_A[MROWS * EMBED];

// ---------------------------------------------------------------------------
// GEMM body: C[m,n] = sum_k A[m,k] * B[n,k] (+ bias[n])   ("NT" layout)
// 128x128 block tile, K-tile 16, 256 threads, 8x8 per-thread microtile.
// M, N, K all multiples of tile sizes (8192/1024/1024) -> no bounds checks.
// ---------------------------------------------------------------------------
__device__ __forceinline__ void gemm_body(
    const float* __restrict__ A, const float* __restrict__ B,
    const float* __restrict__ bias, float* __restrict__ C,
    int K, int N)
{
    __shared__ __align__(16) float As[16][128];
    __shared__ __align__(16) float Bs[16][128];

    const int tid = threadIdx.x;
    const int tx  = tid & 15;
    const int ty  = tid >> 4;
    const int bm  = blockIdx.x * 128;
    const int bn  = blockIdx.y * 128;

    float acc[8][8];
    #pragma unroll
    for (int i = 0; i < 8; i++)
        #pragma unroll
        for (int j = 0; j < 8; j++)
            acc[i][j] = 0.f;

    for (int k0 = 0; k0 < K; k0 += 16) {
        // Load 128x16 A and B tiles (transposed into [k][m] layout).
        #pragma unroll
        for (int i = 0; i < 2; i++) {
            int f   = tid + i * 256;        // 0..511 float4 slots
            int row = f >> 2;               // 0..127
            int kq  = (f & 3) << 2;         // 0,4,8,12
            const float4 av = *(const float4*)&A[(bm + row) * K + k0 + kq];
            As[kq + 0][row] = av.x; As[kq + 1][row] = av.y;
            As[kq + 2][row] = av.z; As[kq + 3][row] = av.w;
            const float4 bv = *(const float4*)&B[(bn + row) * K + k0 + kq];
            Bs[kq + 0][row] = bv.x; Bs[kq + 1][row] = bv.y;
            Bs[kq + 2][row] = bv.z; Bs[kq + 3][row] = bv.w;
        }
        __syncthreads();

        #pragma unroll
        for (int kk = 0; kk < 16; kk++) {
            float a[8], b[8];
            *(float4*)&a[0] = *(const float4*)&As[kk][ty * 4];
            *(float4*)&a[4] = *(const float4*)&As[kk][64 + ty * 4];
            *(float4*)&b[0] = *(const float4*)&Bs[kk][tx * 4];
            *(float4*)&b[4] = *(const float4*)&Bs[kk][64 + tx * 4];
            #pragma unroll
            for (int i = 0; i < 8; i++)
                #pragma unroll
                for (int j = 0; j < 8; j++)
                    acc[i][j] += a[i] * b[j];
        }
        __syncthreads();
    }

    // Epilogue
    #pragma unroll
    for (int i = 0; i < 8; i++) {
        int row = bm + ((i < 4) ? (ty * 4 + i) : (64 + ty * 4 + (i - 4)));
        #pragma unroll
        for (int jb = 0; jb < 2; jb++) {
            int col = bn + jb * 64 + tx * 4;
            float4 v;
            v.x = acc[i][jb * 4 + 0];
            v.y = acc[i][jb * 4 + 1];
            v.z = acc[i][jb * 4 + 2];
            v.w = acc[i][jb * 4 + 3];
            if (bias) {
                v.x += bias[col + 0]; v.y += bias[col + 1];
                v.z += bias[col + 2]; v.w += bias[col + 3];
            }
            *(float4*)&C[row * N + col] = v;
        }
    }
}

// QKV projections fused: blockIdx.z selects weight + destination.
__global__ void __launch_bounds__(256) qkv_kernel(
    const float* __restrict__ x,
    const float* __restrict__ Wq,
    const float* __restrict__ Wk,
    const float* __restrict__ Wv)
{
    const float* B;
    float* C;
    if      (blockIdx.z == 0) { B = Wq; C = g_Q; }
    else if (blockIdx.z == 1) { B = Wk; C = g_K; }
    else                      { B = Wv; C = g_V; }
    gemm_body(x, B, nullptr, C, EMBED, EMBED);
}

// Output projection: out = g_A @ Wo^T + bo
__global__ void __launch_bounds__(256) proj_kernel(
    const float* __restrict__ Wo,
    const float* __restrict__ bo,
    float* __restrict__ out)
{
    gemm_body(g_A, Wo, bo, out, EMBED, EMBED);
}

// ---------------------------------------------------------------------------
// Flash attention (causal): one block = (b, h, 64-query tile).
// 256 threads as 16x16; 4x4 microtiles for the 64x64 S/P/O tiles.
// Shared: Qs [d][r] (stride 68), KPs (K as [d][c], reused as P [k][r]),
//         Vs [k][d]. 3 * 64*68*4 = 52224 B dynamic smem.
// ---------------------------------------------------------------------------
#define ATTN_SMEM (3 * 64 * 68 * 4)

__global__ void __launch_bounds__(256) attn_kernel()
{
    extern __shared__ __align__(16) float sm[];
    float* Qs  = sm;                 // [64 d][stride 68] -> Qs[d*68 + r]
    float* KPs = sm + 64 * 68;       // K: [d*68 + c] ; later P: [k*68 + r]
    float* Vs  = sm + 2 * 64 * 68;   // [k*68 + d]

    const int tid = threadIdx.x;
    const int tx  = tid & 15;
    const int ty  = tid >> 4;
    const int qi  = blockIdx.x;      // query tile 0..31
    const int h   = blockIdx.y;
    const int b   = blockIdx.z;
    const int qrow0 = b * S_LEN + qi * 64;
    const int cb    = h * HDIM;

    // Load Q tile (scaled by 1/sqrt(D) = 0.125), transposed to [d][r].
    for (int idx = tid; idx < 1024; idx += 256) {
        int r = idx >> 4;
        int d = (idx & 15) << 2;
        const float4 qv = *(const float4*)&g_Q[(qrow0 + r) * EMBED + cb + d];
        Qs[(d + 0) * 68 + r] = qv.x * 0.125f;
        Qs[(d + 1) * 68 + r] = qv.y * 0.125f;
        Qs[(d + 2) * 68 + r] = qv.z * 0.125f;
        Qs[(d + 3) * 68 + r] = qv.w * 0.125f;
    }

    float m[4], l[4], o[4][4];
    #pragma unroll
    for (int r = 0; r < 4; r++) {
        m[r] = -1e30f; l[r] = 0.f;
        #pragma unroll
        for (int c = 0; c < 4; c++) o[r][c] = 0.f;
    }

    for (int j = 0; j <= qi; j++) {
        const int krow0 = b * S_LEN + j * 64;
        for (int idx = tid; idx < 1024; idx += 256) {
            int r = idx >> 4;
            int d = (idx & 15) << 2;
            const float4 kv = *(const float4*)&g_K[(krow0 + r) * EMBED + cb + d];
            KPs[(d + 0) * 68 + r] = kv.x;
            KPs[(d + 1) * 68 + r] = kv.y;
            KPs[(d + 2) * 68 + r] = kv.z;
            KPs[(d + 3) * 68 + r] = kv.w;
            const float4 vv = *(const float4*)&g_V[(krow0 + r) * EMBED + cb + d];
            *(float4*)&Vs[r * 68 + d] = vv;
        }
        __syncthreads();   // also covers the Q load on the first iteration

        // S = Q * K^T  (thread: rows 4ty..+3, key cols 4tx..+3)
        float s[4][4];
        #pragma unroll
        for (int r = 0; r < 4; r++)
            #pragma unroll
            for (int c = 0; c < 4; c++) s[r][c] = 0.f;

        #pragma unroll 8
        for (int kk = 0; kk < 64; kk++) {
            float qa[4], kb[4];
            *(float4*)qa = *(const float4*)&Qs[kk * 68 + ty * 4];
            *(float4*)kb = *(const float4*)&KPs[kk * 68 + tx * 4];
            #pragma unroll
            for (int r = 0; r < 4; r++)
                #pragma unroll
                for (int c = 0; c < 4; c++)
                    s[r][c] += qa[r] * kb[c];
        }

        if (j == qi) {   // causal mask on the diagonal tile
            #pragma unroll
            for (int r = 0; r < 4; r++)
                #pragma unroll
                for (int c = 0; c < 4; c++)
                    if (tx * 4 + c > ty * 4 + r) s[r][c] = -1e30f;
        }

        // Online softmax (row reductions across the 16 tx-threads via shfl;
        // lane = (ty&1)*16 + tx, so xor masks 1,2,4,8 stay within a row group).
        float p[4][4];
        #pragma unroll
        for (int r = 0; r < 4; r++) {
            float mx = fmaxf(fmaxf(s[r][0], s[r][1]), fmaxf(s[r][2], s[r][3]));
            mx = fmaxf(mx, __shfl_xor_sync(0xffffffffu, mx, 1));
            mx = fmaxf(mx, __shfl_xor_sync(0xffffffffu, mx, 2));
            mx = fmaxf(mx, __shfl_xor_sync(0xffffffffu, mx, 4));
            mx = fmaxf(mx, __shfl_xor_sync(0xffffffffu, mx, 8));
            const float mn = fmaxf(m[r], mx);
            float rs = 0.f;
            #pragma unroll
            for (int c = 0; c < 4; c++) {
                p[r][c] = __expf(s[r][c] - mn);
                rs += p[r][c];
            }
            rs += __shfl_xor_sync(0xffffffffu, rs, 1);
            rs += __shfl_xor_sync(0xffffffffu, rs, 2);
            rs += __shfl_xor_sync(0xffffffffu, rs, 4);
            rs += __shfl_xor_sync(0xffffffffu, rs, 8);
            const float sc = __expf(m[r] - mn);
            l[r] = l[r] * sc + rs;
            m[r] = mn;
            #pragma unroll
            for (int c = 0; c < 4; c++) o[r][c] *= sc;
        }

        __syncthreads();   // everyone done reading KPs as K
        // Write P transposed: P[k][r] so PV uses the same microtile pattern.
        #pragma unroll
        for (int r = 0; r < 4; r++)
            #pragma unroll
            for (int c = 0; c < 4; c++)
                KPs[(tx * 4 + c) * 68 + ty * 4 + r] = p[r][c];
        __syncthreads();

        // O += P * V
        #pragma unroll 8
        for (int kk = 0; kk < 64; kk++) {
            float pa[4], vb[4];
            *(float4*)pa = *(const float4*)&KPs[kk * 68 + ty * 4];
            *(float4*)vb = *(const float4*)&Vs[kk * 68 + tx * 4];
            #pragma unroll
            for (int r = 0; r < 4; r++)
                #pragma unroll
                for (int c = 0; c < 4; c++)
                    o[r][c] += pa[r] * vb[c];
        }
        __syncthreads();   // before next iteration overwrites KPs/Vs
    }

    // Normalize and store to g_A at [b*S + q, h*64 + d]
    #pragma unroll
    for (int r = 0; r < 4; r++) {
        const float inv = 1.0f / l[r];
        float4 v;
        v.x = o[r][0] * inv; v.y = o[r][1] * inv;
        v.z = o[r][2] * inv; v.w = o[r][3] * inv;
        *(float4*)&g_A[(qrow0 + ty * 4 + r) * EMBED + cb + tx * 4] = v;
    }
}

// ---------------------------------------------------------------------------
extern "C" void kernel_launch(void* const* d_in, const int* in_sizes, int n_in,
                              void* d_out, int out_size)
{
    const float* x  = (const float*)d_in[0];
    const float* Wq = (const float*)d_in[1];
    const float* Wk = (const float*)d_in[2];
    const float* Wv = (const float*)d_in[3];
    const float* Wo = (const float*)d_in[4];
    const float* bo = (const float*)d_in[5];
    float* out = (float*)d_out;

    static bool attr_set = false;
    // cudaFuncSetAttribute is idempotent & capture-safe; call unconditionally.
    cudaFuncSetAttribute(attn_kernel,
                         cudaFuncAttributeMaxDynamicSharedMemorySize, ATTN_SMEM);
    (void)attr_set;

    // 1) Q, K, V projections (fused into one launch via blockIdx.z)
    dim3 gq(MROWS / 128, EMBED / 128, 3);
    qkv_kernel<<<gq, 256>>>(x, Wq, Wk, Wv);

    // 2) Causal flash attention
    dim3 ga(S_LEN / 64, HEADS, BATCH);
    attn_kernel<<<ga, 256, ATTN_SMEM>>>();

    // 3) Output projection + bias
    dim3 gp(MROWS / 128, EMBED / 128, 1);
    proj_kernel<<<gp, 256>>>(Wo, bo, out);
}

// round 3
// speedup vs baseline: 1.3470x; 1.3470x over previous
#include <cuda_runtime.h>
#include <cuda_bf16.h>
#include <cstdint>

#define S_LEN  2048
#define BATCH  4
#define EMBED  1024
#define HEADS  16
#define HDIM   64
#define MROWS  (BATCH * S_LEN)   // 8192
#define KP     3072              // 3-term split K' = 3 * 1024

// ---------------------------------------------------------------------------
// Scratch (allocation-free device globals)
// ---------------------------------------------------------------------------
__device__ __align__(16) float g_Q[MROWS * EMBED];
__device__ __align__(16) float g_K[MROWS * EMBED];
__device__ __align__(16) float g_V[MROWS * EMBED];
__device__ __align__(16) float g_A[MROWS * EMBED];
__device__ __align__(16) __nv_bfloat16 g_Asplit[(size_t)MROWS * KP];   // 48 MB
__device__ __align__(16) __nv_bfloat16 g_Bqkv[(size_t)3 * EMBED * KP]; // 18 MB
__device__ __align__(16) __nv_bfloat16 g_Bo[(size_t)EMBED * KP];       //  6 MB

// ---------------------------------------------------------------------------
// PTX helpers (compute_100-safe only: cp.async, ldmatrix, mma.sync)
// ---------------------------------------------------------------------------
__device__ __forceinline__ uint32_t smem_u32(const void* p) {
    uint32_t a;
    asm("{ .reg .u64 t; cvta.to.shared.u64 t, %1; cvt.u32.u64 %0, t; }"
        : "=r"(a) : "l"(p));
    return a;
}

__device__ __forceinline__ void cpasync16(uint32_t s, const void* g) {
    asm volatile("cp.async.cg.shared.global [%0], [%1], 16;" :: "r"(s), "l"(g));
}

#define CP_COMMIT()  asm volatile("cp.async.commit_group;" ::: "memory")
#define CP_WAIT(n)   asm volatile("cp.async.wait_group %0;" :: "n"(n) : "memory")

#define LDSM_X4(r0, r1, r2, r3, addr) \
    asm volatile("ldmatrix.sync.aligned.m8n8.x4.shared.b16 {%0,%1,%2,%3}, [%4];" \
        : "=r"(r0), "=r"(r1), "=r"(r2), "=r"(r3) : "r"(addr))
#define LDSM_X2(r0, r1, addr) \
    asm volatile("ldmatrix.sync.aligned.m8n8.x2.shared.b16 {%0,%1}, [%2];" \
        : "=r"(r0), "=r"(r1) : "r"(addr))

#define MMA16816(d, a, b) \
    asm volatile("mma.sync.aligned.m16n8k16.row.col.f32.bf16.bf16.f32 " \
        "{%0,%1,%2,%3}, {%4,%5,%6,%7}, {%8,%9}, {%0,%1,%2,%3};" \
        : "+f"((d)[0]), "+f"((d)[1]), "+f"((d)[2]), "+f"((d)[3]) \
        : "r"((a)[0]), "r"((a)[1]), "r"((a)[2]), "r"((a)[3]), \
          "r"((b)[0]), "r"((b)[1]))

// ---------------------------------------------------------------------------
// fp32 -> bf16 hi/lo split conversion kernels
// A pattern: [hi | hi | lo]   B pattern: [hi | lo | hi]
// ---------------------------------------------------------------------------
__device__ __forceinline__ void split4(const float4 v, __nv_bfloat162& h01,
                                       __nv_bfloat162& h23, __nv_bfloat162& l01,
                                       __nv_bfloat162& l23) {
    float f[4] = {v.x, v.y, v.z, v.w};
    __nv_bfloat16 h[4], l[4];
#pragma unroll
    for (int i = 0; i < 4; i++) {
        h[i] = __float2bfloat16(f[i]);
        l[i] = __float2bfloat16(f[i] - __bfloat162float(h[i]));
    }
    h01 = __nv_bfloat162(h[0], h[1]); h23 = __nv_bfloat162(h[2], h[3]);
    l01 = __nv_bfloat162(l[0], l[1]); l23 = __nv_bfloat162(l[2], l[3]);
}

__global__ void __launch_bounds__(256) convA_kernel(
    const float* __restrict__ src, __nv_bfloat16* __restrict__ dst, int rows)
{
    int idx = blockIdx.x * 256 + threadIdx.x;
    if (idx >= rows * (EMBED / 4)) return;
    int r  = idx >> 8;
    int c4 = (idx & 255) << 2;
    float4 v = *(const float4*)&src[(size_t)r * EMBED + c4];
    __nv_bfloat162 h01, h23, l01, l23;
    split4(v, h01, h23, l01, l23);
    __nv_bfloat162* d0 = (__nv_bfloat162*)&dst[(size_t)r * KP + c4];
    __nv_bfloat162* d1 = (__nv_bfloat162*)&dst[(size_t)r * KP + 1024 + c4];
    __nv_bfloat162* d2 = (__nv_bfloat162*)&dst[(size_t)r * KP + 2048 + c4];
    d0[0] = h01; d0[1] = h23;     // hi
    d1[0] = h01; d1[1] = h23;     // hi
    d2[0] = l01; d2[1] = l23;     // lo
}

__global__ void __launch_bounds__(256) convW_kernel(
    const float* __restrict__ W0, const float* __restrict__ W1,
    const float* __restrict__ W2, __nv_bfloat16* __restrict__ dst)
{
    const float* W = (blockIdx.y == 0) ? W0 : (blockIdx.y == 1) ? W1 : W2;
    __nv_bfloat16* d = dst + (size_t)blockIdx.y * EMBED * KP;
    int idx = blockIdx.x * 256 + threadIdx.x;
    if (idx >= EMBED * (EMBED / 4)) return;
    int r  = idx >> 8;
    int c4 = (idx & 255) << 2;
    float4 v = *(const float4*)&W[(size_t)r * EMBED + c4];
    __nv_bfloat162 h01, h23, l01, l23;
    split4(v, h01, h23, l01, l23);
    __nv_bfloat162* d0 = (__nv_bfloat162*)&d[(size_t)r * KP + c4];
    __nv_bfloat162* d1 = (__nv_bfloat162*)&d[(size_t)r * KP + 1024 + c4];
    __nv_bfloat162* d2 = (__nv_bfloat162*)&d[(size_t)r * KP + 2048 + c4];
    d0[0] = h01; d0[1] = h23;     // hi
    d1[0] = l01; d1[1] = l23;     // lo
    d2[0] = h01; d2[1] = h23;     // hi
}

// ---------------------------------------------------------------------------
// HMMA bf16 GEMM:  C[m, n] = sum_k A'[m,k] * B'[n,k]
// 128x128 CTA tile, BK=32, 3-stage cp.async pipeline.
// 8 warps as 2(M) x 4(N); warp tile 64x32 via m16n8k16.
// Smem rows padded to 40 bf16 (80 B) -> conflict-free ldmatrix.
// grid.x = N/128 (B' stays hot in L2), grid.y = M/128.
// seg = bn/1024 selects C0/C1/C2 (fused qkv); col stride EMBED.
// ---------------------------------------------------------------------------
#define BM 128
#define BN 128
#define BK 32
#define STAGES 3
#define KT (KP / BK)                  // 96
#define ASTR 40                       // smem row stride in bf16 elems
#define TILE_E (128 * ASTR)           // elems per operand tile
#define STAGE_E (2 * TILE_E)
#define GEMM_SMEM (STAGES * STAGE_E * 2)   // 61440 bytes

__global__ void __launch_bounds__(256, 2) gemm_bf16_kernel(
    const __nv_bfloat16* __restrict__ Abuf, const __nv_bfloat16* __restrict__ Bbuf,
    float* __restrict__ C0, float* __restrict__ C1, float* __restrict__ C2,
    const float* __restrict__ bias)
{
    extern __shared__ __align__(16) __nv_bfloat16 sm[];
    const uint32_t smb = smem_u32(sm);
    const int tid  = threadIdx.x;
    const int wid  = tid >> 5;
    const int lane = tid & 31;
    const int wm = wid >> 2;          // 0..1  (M)
    const int wn = wid & 3;           // 0..3  (N)
    const int bn = blockIdx.x * BN;
    const int bm = blockIdx.y * BM;

    float acc[4][4][4];
#pragma unroll
    for (int i = 0; i < 4; i++)
#pragma unroll
        for (int j = 0; j < 4; j++)
#pragma unroll
            for (int k = 0; k < 4; k++) acc[i][j][k] = 0.f;

    // per-thread cp.async chunk coords (2 chunks per operand)
    const int r0c = (tid * 2) >> 2;            // row of first chunk
    const int c0c = (tid * 2) & 3;             // 16B chunk idx in row
    const int r1c = (tid * 2 + 1) >> 2;
    const int c1c = (tid * 2 + 1) & 3;

    auto load_tile = [&](int kt, int slot) {
        const __nv_bfloat16* Ag = Abuf + (size_t)bm * KP + kt * BK;
        const __nv_bfloat16* Bg = Bbuf + (size_t)bn * KP + kt * BK;
        uint32_t sA = smb + slot * STAGE_E * 2;
        uint32_t sB = sA + TILE_E * 2;
        cpasync16(sA + (r0c * ASTR + c0c * 8) * 2, Ag + (size_t)r0c * KP + c0c * 8);
        cpasync16(sA + (r1c * ASTR + c1c * 8) * 2, Ag + (size_t)r1c * KP + c1c * 8);
        cpasync16(sB + (r0c * ASTR + c0c * 8) * 2, Bg + (size_t)r0c * KP + c0c * 8);
        cpasync16(sB + (r1c * ASTR + c1c * 8) * 2, Bg + (size_t)r1c * KP + c1c * 8);
    };

    // ldmatrix per-lane base offsets (in bytes, k=0 position)
    const int aRow = wm * 64 + (lane & 15);          // + mf*16
    const int aKof = (lane >> 4) << 3;               // 0 or 8
    const int bRow = wn * 32 + (lane & 7);           // + nf*8
    const int bKof = ((lane >> 3) & 1) << 3;         // 0 or 8

#pragma unroll
    for (int s = 0; s < STAGES - 1; s++) {
        load_tile(s, s);
        CP_COMMIT();
    }

    for (int kt = 0; kt < KT; kt++) {
        CP_WAIT(STAGES - 2);
        __syncthreads();                 // slot kt%STAGES ready; prev compute done

        if (kt + STAGES - 1 < KT)
            load_tile(kt + STAGES - 1, (kt + STAGES - 1) % STAGES);
        CP_COMMIT();

        const uint32_t sA = smb + (kt % STAGES) * STAGE_E * 2;
        const uint32_t sB = sA + TILE_E * 2;

#pragma unroll
        for (int ks = 0; ks < 2; ks++) {          // two k16 steps in BK=32
            const int kk = ks * 16;
            uint32_t a[4][4], b[4][2];
#pragma unroll
            for (int mf = 0; mf < 4; mf++) {
                uint32_t addr = sA + ((aRow + mf * 16) * ASTR + kk + aKof) * 2;
                LDSM_X4(a[mf][0], a[mf][1], a[mf][2], a[mf][3], addr);
            }
#pragma unroll
            for (int nf = 0; nf < 4; nf++) {
                uint32_t addr = sB + ((bRow + nf * 8) * ASTR + kk + bKof) * 2;
                LDSM_X2(b[nf][0], b[nf][1], addr);
            }
#pragma unroll
            for (int mf = 0; mf < 4; mf++)
#pragma unroll
                for (int nf = 0; nf < 4; nf++)
                    MMA16816(acc[mf][nf], a[mf], b[nf]);
        }
    }

    // Epilogue: c frag (m16n8): d0,d1 -> (gid, tig*2 + {0,1}); d2,d3 -> gid+8.
    const int gid = lane >> 2;
    const int tig = lane & 3;
    const int seg = bn >> 10;
    float* C = (seg == 0) ? C0 : (seg == 1) ? C1 : C2;
    const int cb = (bn & 1023) + wn * 32;

#pragma unroll
    for (int mf = 0; mf < 4; mf++) {
        const int row0 = bm + wm * 64 + mf * 16 + gid;
#pragma unroll
        for (int nf = 0; nf < 4; nf++) {
            const int col = cb + nf * 8 + tig * 2;
            float2 v0, v1;
            v0.x = acc[mf][nf][0]; v0.y = acc[mf][nf][1];
            v1.x = acc[mf][nf][2]; v1.y = acc[mf][nf][3];
            if (bias) {
                const float b0 = bias[col], b1 = bias[col + 1];
                v0.x += b0; v0.y += b1;
                v1.x += b0; v1.y += b1;
            }
            *(float2*)&C[(size_t)row0 * EMBED + col] = v0;
            *(float2*)&C[(size_t)(row0 + 8) * EMBED + col] = v1;
        }
    }
}

// ---------------------------------------------------------------------------
// Flash attention (causal), fp32 — unchanged.
// ---------------------------------------------------------------------------
#define ATTN_SMEM (3 * 64 * 68 * 4)

__global__ void __launch_bounds__(256) attn_kernel()
{
    extern __shared__ __align__(16) float smf[];
    float* Qs  = smf;
    float* KPs = smf + 64 * 68;
    float* Vs  = smf + 2 * 64 * 68;

    const int tid = threadIdx.x;
    const int tx  = tid & 15;
    const int ty  = tid >> 4;
    const int qi  = blockIdx.x;
    const int h   = blockIdx.y;
    const int b   = blockIdx.z;
    const int qrow0 = b * S_LEN + qi * 64;
    const int cb    = h * HDIM;

    for (int idx = tid; idx < 1024; idx += 256) {
        int r = idx >> 4;
        int d = (idx & 15) << 2;
        const float4 qv = *(const float4*)&g_Q[(size_t)(qrow0 + r) * EMBED + cb + d];
        Qs[(d + 0) * 68 + r] = qv.x * 0.125f;
        Qs[(d + 1) * 68 + r] = qv.y * 0.125f;
        Qs[(d + 2) * 68 + r] = qv.z * 0.125f;
        Qs[(d + 3) * 68 + r] = qv.w * 0.125f;
    }

    float m[4], l[4], o[4][4];
#pragma unroll
    for (int r = 0; r < 4; r++) {
        m[r] = -1e30f; l[r] = 0.f;
#pragma unroll
        for (int c = 0; c < 4; c++) o[r][c] = 0.f;
    }

    for (int j = 0; j <= qi; j++) {
        const int krow0 = b * S_LEN + j * 64;
        for (int idx = tid; idx < 1024; idx += 256) {
            int r = idx >> 4;
            int d = (idx & 15) << 2;
            const float4 kv = *(const float4*)&g_K[(size_t)(krow0 + r) * EMBED + cb + d];
            KPs[(d + 0) * 68 + r] = kv.x;
            KPs[(d + 1) * 68 + r] = kv.y;
            KPs[(d + 2) * 68 + r] = kv.z;
            KPs[(d + 3) * 68 + r] = kv.w;
            const float4 vv = *(const float4*)&g_V[(size_t)(krow0 + r) * EMBED + cb + d];
            *(float4*)&Vs[r * 68 + d] = vv;
        }
        __syncthreads();

        float s[4][4];
#pragma unroll
        for (int r = 0; r < 4; r++)
#pragma unroll
            for (int c = 0; c < 4; c++) s[r][c] = 0.f;

#pragma unroll 8
        for (int kk = 0; kk < 64; kk++) {
            float qa[4], kb[4];
            *(float4*)qa = *(const float4*)&Qs[kk * 68 + ty * 4];
            *(float4*)kb = *(const float4*)&KPs[kk * 68 + tx * 4];
#pragma unroll
            for (int r = 0; r < 4; r++)
#pragma unroll
                for (int c = 0; c < 4; c++)
                    s[r][c] += qa[r] * kb[c];
        }

        if (j == qi) {
#pragma unroll
            for (int r = 0; r < 4; r++)
#pragma unroll
                for (int c = 0; c < 4; c++)
                    if (tx * 4 + c > ty * 4 + r) s[r][c] = -1e30f;
        }

        float p[4][4];
#pragma unroll
        for (int r = 0; r < 4; r++) {
            float mx = fmaxf(fmaxf(s[r][0], s[r][1]), fmaxf(s[r][2], s[r][3]));
            mx = fmaxf(mx, __shfl_xor_sync(0xffffffffu, mx, 1));
            mx = fmaxf(mx, __shfl_xor_sync(0xffffffffu, mx, 2));
            mx = fmaxf(mx, __shfl_xor_sync(0xffffffffu, mx, 4));
            mx = fmaxf(mx, __shfl_xor_sync(0xffffffffu, mx, 8));
            const float mn = fmaxf(m[r], mx);
            float rs = 0.f;
#pragma unroll
            for (int c = 0; c < 4; c++) {
                p[r][c] = __expf(s[r][c] - mn);
                rs += p[r][c];
            }
            rs += __shfl_xor_sync(0xffffffffu, rs, 1);
            rs += __shfl_xor_sync(0xffffffffu, rs, 2);
            rs += __shfl_xor_sync(0xffffffffu, rs, 4);
            rs += __shfl_xor_sync(0xffffffffu, rs, 8);
            const float sc = __expf(m[r] - mn);
            l[r] = l[r] * sc + rs;
            m[r] = mn;
#pragma unroll
            for (int c = 0; c < 4; c++) o[r][c] *= sc;
        }

        __syncthreads();
#pragma unroll
        for (int r = 0; r < 4; r++)
#pragma unroll
            for (int c = 0; c < 4; c++)
                KPs[(tx * 4 + c) * 68 + ty * 4 + r] = p[r][c];
        __syncthreads();

#pragma unroll 8
        for (int kk = 0; kk < 64; kk++) {
            float pa[4], vb[4];
            *(float4*)pa = *(const float4*)&KPs[kk * 68 + ty * 4];
            *(float4*)vb = *(const float4*)&Vs[kk * 68 + tx * 4];
#pragma unroll
            for (int r = 0; r < 4; r++)
#pragma unroll
                for (int c = 0; c < 4; c++)
                    o[r][c] += pa[r] * vb[c];
        }
        __syncthreads();
    }

#pragma unroll
    for (int r = 0; r < 4; r++) {
        const float inv = 1.0f / l[r];
        float4 v;
        v.x = o[r][0] * inv; v.y = o[r][1] * inv;
        v.z = o[r][2] * inv; v.w = o[r][3] * inv;
        *(float4*)&g_A[(size_t)(qrow0 + ty * 4 + r) * EMBED + cb + tx * 4] = v;
    }
}

// ---------------------------------------------------------------------------
extern "C" void kernel_launch(void* const* d_in, const int* in_sizes, int n_in,
                              void* d_out, int out_size)
{
    const float* x  = (const float*)d_in[0];
    const float* Wq = (const float*)d_in[1];
    const float* Wk = (const float*)d_in[2];
    const float* Wv = (const float*)d_in[3];
    const float* Wo = (const float*)d_in[4];
    const float* bo = (const float*)d_in[5];
    float* out = (float*)d_out;

    cudaFuncSetAttribute(gemm_bf16_kernel,
                         cudaFuncAttributeMaxDynamicSharedMemorySize, GEMM_SMEM);
    cudaFuncSetAttribute(attn_kernel,
                         cudaFuncAttributeMaxDynamicSharedMemorySize, ATTN_SMEM);

    __nv_bfloat16 *gAs, *gBqkv, *gBo;
    float *gq, *gk, *gv, *ga;
    cudaGetSymbolAddress((void**)&gAs,  g_Asplit);
    cudaGetSymbolAddress((void**)&gBqkv, g_Bqkv);
    cudaGetSymbolAddress((void**)&gBo,  g_Bo);
    cudaGetSymbolAddress((void**)&gq, g_Q);
    cudaGetSymbolAddress((void**)&gk, g_K);
    cudaGetSymbolAddress((void**)&gv, g_V);
    cudaGetSymbolAddress((void**)&ga, g_A);

    // 1) fp32 -> bf16 hi/lo splits
    convA_kernel<<<MROWS, 256>>>(x, gAs, MROWS);
    convW_kernel<<<dim3(EMBED, 3), 256>>>(Wq, Wk, Wv, gBqkv);
    convW_kernel<<<dim3(EMBED, 1), 256>>>(Wo, Wo, Wo, gBo);

    // 2) fused QKV projection: [8192 x 3072] = A' @ Bqkv'^T
    gemm_bf16_kernel<<<dim3(3 * EMBED / BN, MROWS / BM), 256, GEMM_SMEM>>>(
        gAs, gBqkv, gq, gk, gv, nullptr);

    // 3) causal flash attention (fp32)
    attn_kernel<<<dim3(S_LEN / 64, HEADS, BATCH), 256, ATTN_SMEM>>>();

    // 4) attention output -> bf16 split, then output projection + bias
    convA_kernel<<<MROWS, 256>>>(ga, gAs, MROWS);
    gemm_bf16_kernel<<<dim3(EMBED / BN, MROWS / BM), 256, GEMM_SMEM>>>(
        gAs, gBo, out, out, out, bo);
}